// round 7
// baseline (speedup 1.0000x reference)
#include <cuda_runtime.h>

// VTBPR fused kernel (R7): R6 phased/32-reg structure + evict-first writes.
//   score[b] = item_beta[i] + user_beta[u] + <ug,ig> + <tv,vf_b> + <tt,tf_b>
//   metapath[b,0,p,l,:] = ug if path_type==0, ig if ==1, else 0
//
// d_out = [ score (B floats) | metapath (B*16*512 floats) ]
//
// R7 theory: inputs are identical every graph replay; the ~100MB input
// working set fits the persistent 126MB L2 but gets thrashed by the 268MB
// write stream. __stcs (evict-first) on the metapath stores preserves L2
// for the reads -> DRAM traffic ~310MB -> ~270MB. R3 tried this but was
// confounded by a 56-reg occupancy regression; R6's phased form stays at
// 32 regs, isolating the cache-policy effect.

#define HIDDEN 512
#define VEC    (HIDDEN / 4)   // 128 float4 lanes
#define PL     16             // P*L

__global__ void __launch_bounds__(VEC, 16)
vtbpr_kernel(const float* __restrict__ user_gama,
             const float* __restrict__ item_gama,
             const float* __restrict__ user_beta,
             const float* __restrict__ item_beta,
             const float* __restrict__ theta_user_visual,
             const float* __restrict__ theta_user_text,
             const float* __restrict__ visual_features,
             const float* __restrict__ textural_features,
             const int*   __restrict__ user_idx,
             const int*   __restrict__ item_idx,
             const int*   __restrict__ path_type,
             float* __restrict__ out,
             int B)
{
    const int b   = blockIdx.x;
    const int tid = threadIdx.x;           // 0..127

    __shared__ int   pt[PL];
    __shared__ float wsum[VEC / 32];

    const int u = user_idx[b];
    const int i = item_idx[b];

    if (tid < PL) pt[tid] = path_type[b * PL + tid];

    // ---- Phase 1: ug/ig -> metapath scatter + first dot ----
    const float4 ug4 = ((const float4*)(user_gama + (size_t)u * HIDDEN))[tid];
    const float4 ig4 = ((const float4*)(item_gama + (size_t)i * HIDDEN))[tid];

    __syncthreads();   // orders pt STS; arrives with ug/ig LDGs in flight

    float4* mp = (float4*)(out + B + (size_t)b * PL * HIDDEN);
    const float4 zero4 = make_float4(0.f, 0.f, 0.f, 0.f);

    #pragma unroll
    for (int j = 0; j < PL; j++) {
        const int t = pt[j];
        const float4 v = (t == 0) ? ug4 : ((t == 1) ? ig4 : zero4);
        __stcs(&mp[(size_t)j * VEC + tid], v);   // evict-first: don't thrash L2
    }

    float partial =
        ug4.x * ig4.x + ug4.y * ig4.y + ug4.z * ig4.z + ug4.w * ig4.w;

    // ---- Phase 2: tv/vf dot (ug/ig registers now dead) ----
    {
        const float4 tv4 = ((const float4*)(theta_user_visual + (size_t)u * HIDDEN))[tid];
        const float4 vf4 = ((const float4*)(visual_features   + (size_t)b * HIDDEN))[tid];
        partial += tv4.x * vf4.x + tv4.y * vf4.y + tv4.z * vf4.z + tv4.w * vf4.w;
    }

    // ---- Phase 3: tt/tf dot ----
    {
        const float4 tt4 = ((const float4*)(theta_user_text     + (size_t)u * HIDDEN))[tid];
        const float4 tf4 = ((const float4*)(textural_features   + (size_t)b * HIDDEN))[tid];
        partial += tt4.x * tf4.x + tt4.y * tf4.y + tt4.z * tf4.z + tt4.w * tf4.w;
    }

    // ---- Reduce + epilogue ----
    #pragma unroll
    for (int off = 16; off > 0; off >>= 1)
        partial += __shfl_xor_sync(0xFFFFFFFFu, partial, off);

    if ((tid & 31) == 0) wsum[tid >> 5] = partial;
    __syncthreads();

    if (tid == 0) {
        float s = user_beta[u] + item_beta[i];
        #pragma unroll
        for (int w = 0; w < VEC / 32; w++) s += wsum[w];
        out[b] = s;
    }
}

extern "C" void kernel_launch(void* const* d_in, const int* in_sizes, int n_in,
                              void* d_out, int out_size)
{
    const float* user_gama          = (const float*)d_in[0];
    const float* item_gama          = (const float*)d_in[1];
    const float* user_beta          = (const float*)d_in[2];
    const float* item_beta          = (const float*)d_in[3];
    const float* theta_user_visual  = (const float*)d_in[4];
    const float* theta_user_text    = (const float*)d_in[5];
    const float* visual_features    = (const float*)d_in[6];
    const float* textural_features  = (const float*)d_in[7];
    const int*   user_idx           = (const int*)d_in[8];
    const int*   item_idx           = (const int*)d_in[9];
    const int*   path_type          = (const int*)d_in[10];

    const int B = in_sizes[8];  // 8192

    vtbpr_kernel<<<B, VEC>>>(user_gama, item_gama, user_beta, item_beta,
                             theta_user_visual, theta_user_text,
                             visual_features, textural_features,
                             user_idx, item_idx, path_type,
                             (float*)d_out, B);
}

// round 8
// speedup vs baseline: 1.0229x; 1.0229x over previous
#include <cuda_runtime.h>

// VTBPR fused kernel (R8): R2 structure (best measured: 56.5us ncu) with
// write-through metapath stores.
//   score[b] = item_beta[i] + user_beta[u] + <ug,ig> + <tv,vf_b> + <tt,tf_b>
//   metapath[b,0,p,l,:] = ug if path_type==0, ig if ==1, else 0
//
// d_out = [ score (B floats) | metapath (B*16*512 floats) ]
//
// R8 theory: R6/R7 falsified occupancy (40->88% occ, no delta) and .cs
// evict-first (no delta). Nothing is saturated (DRAM 68%, LTS 42%,
// issue 14%). Remaining suspect: L2 write-ALLOCATION machinery on the
// 268MB stream -- .cs still allocates lines; __stwt does not. Full
// 128B-sector-aligned warp stores -> WT has no partial-sector penalty.

#define HIDDEN 512
#define VEC    (HIDDEN / 4)   // 128 float4 lanes
#define PL     16             // P*L

__global__ void __launch_bounds__(VEC, 8)
vtbpr_kernel(const float* __restrict__ user_gama,
             const float* __restrict__ item_gama,
             const float* __restrict__ user_beta,
             const float* __restrict__ item_beta,
             const float* __restrict__ theta_user_visual,
             const float* __restrict__ theta_user_text,
             const float* __restrict__ visual_features,
             const float* __restrict__ textural_features,
             const int*   __restrict__ user_idx,
             const int*   __restrict__ item_idx,
             const int*   __restrict__ path_type,
             float* __restrict__ out,
             int B)
{
    const int b   = blockIdx.x;
    const int tid = threadIdx.x;           // 0..127

    __shared__ int   pt[PL];
    __shared__ float wsum[VEC / 32];

    const int u = user_idx[b];
    const int i = item_idx[b];

    if (tid < PL) pt[tid] = path_type[b * PL + tid];

    const float4* ug_p = (const float4*)(user_gama         + (size_t)u * HIDDEN);
    const float4* ig_p = (const float4*)(item_gama         + (size_t)i * HIDDEN);
    const float4* tv_p = (const float4*)(theta_user_visual + (size_t)u * HIDDEN);
    const float4* tt_p = (const float4*)(theta_user_text   + (size_t)u * HIDDEN);
    const float4* vf_p = (const float4*)(visual_features   + (size_t)b * HIDDEN);
    const float4* tf_p = (const float4*)(textural_features + (size_t)b * HIDDEN);

    // Front-batch all six loads (max MLP; best measured structure = R2).
    const float4 ug4 = ug_p[tid];
    const float4 ig4 = ig_p[tid];
    const float4 tv4 = tv_p[tid];
    const float4 tt4 = tt_p[tid];
    const float4 vf4 = vf_p[tid];
    const float4 tf4 = tf_p[tid];

    // Dot products + warp reduce
    float partial =
        ug4.x * ig4.x + ug4.y * ig4.y + ug4.z * ig4.z + ug4.w * ig4.w +
        tv4.x * vf4.x + tv4.y * vf4.y + tv4.z * vf4.z + tv4.w * vf4.w +
        tt4.x * tf4.x + tt4.y * tf4.y + tt4.z * tf4.z + tt4.w * tf4.w;

    #pragma unroll
    for (int off = 16; off > 0; off >>= 1)
        partial += __shfl_xor_sync(0xFFFFFFFFu, partial, off);

    if ((tid & 31) == 0) wsum[tid >> 5] = partial;
    __syncthreads();

    if (tid == 0) {
        float s = user_beta[u] + item_beta[i];
        #pragma unroll
        for (int w = 0; w < VEC / 32; w++) s += wsum[w];
        out[b] = s;
    }

    // Metapath scatter: 16 coalesced write-through STG.128 per thread.
    // Each warp covers full 128B sectors -> no partial-sector WT penalty.
    float4* mp = (float4*)(out + B + (size_t)b * PL * HIDDEN);
    const float4 zero4 = make_float4(0.f, 0.f, 0.f, 0.f);

    #pragma unroll
    for (int j = 0; j < PL; j++) {
        const int t = pt[j];
        const float4 v = (t == 0) ? ug4 : ((t == 1) ? ig4 : zero4);
        __stwt(&mp[(size_t)j * VEC + tid], v);
    }
}

extern "C" void kernel_launch(void* const* d_in, const int* in_sizes, int n_in,
                              void* d_out, int out_size)
{
    const float* user_gama          = (const float*)d_in[0];
    const float* item_gama          = (const float*)d_in[1];
    const float* user_beta          = (const float*)d_in[2];
    const float* item_beta          = (const float*)d_in[3];
    const float* theta_user_visual  = (const float*)d_in[4];
    const float* theta_user_text    = (const float*)d_in[5];
    const float* visual_features    = (const float*)d_in[6];
    const float* textural_features  = (const float*)d_in[7];
    const int*   user_idx           = (const int*)d_in[8];
    const int*   item_idx           = (const int*)d_in[9];
    const int*   path_type          = (const int*)d_in[10];

    const int B = in_sizes[8];  // 8192

    vtbpr_kernel<<<B, VEC>>>(user_gama, item_gama, user_beta, item_beta,
                             theta_user_visual, theta_user_text,
                             visual_features, textural_features,
                             user_idx, item_idx, path_type,
                             (float*)d_out, B);
}

// round 9
// speedup vs baseline: 1.0502x; 1.0267x over previous
#include <cuda_runtime.h>
#include <cstdint>

// VTBPR fused kernel (R9): R2 structure + L2 evict_last policy on reads.
//   score[b] = item_beta[i] + user_beta[u] + <ug,ig> + <tv,vf_b> + <tt,tf_b>
//   metapath[b,0,p,l,:] = ug if path_type==0, ig if ==1, else 0
//
// d_out = [ score (B floats) | metapath (B*16*512 floats) ]
//
// R9 theory: 311MB DRAM/launch = 268MB writes + 43MB read misses. The
// 96MB read working set fits the persistent 126MB L2 but the write
// stream evicts it each replay. R7/R8 attacked this from the write side
// (.cs/.wt) -- neutral. R9 pins the reads: createpolicy evict_last +
// ld.global.L2::cache_hint on all six vector loads. Writes stay plain
// (normal priority cannot evict evict_last lines).

#define HIDDEN 512
#define VEC    (HIDDEN / 4)   // 128 float4 lanes
#define PL     16             // P*L

__device__ __forceinline__ uint64_t policy_evict_last() {
    uint64_t p;
    asm("createpolicy.fractional.L2::evict_last.b64 %0, 1.0;" : "=l"(p));
    return p;
}

__device__ __forceinline__ float4 ld_el(const float4* a, uint64_t pol) {
    float4 v;
    asm("ld.global.L2::cache_hint.v4.f32 {%0,%1,%2,%3}, [%4], %5;"
        : "=f"(v.x), "=f"(v.y), "=f"(v.z), "=f"(v.w)
        : "l"(a), "l"(pol));
    return v;
}

__global__ void __launch_bounds__(VEC, 8)
vtbpr_kernel(const float* __restrict__ user_gama,
             const float* __restrict__ item_gama,
             const float* __restrict__ user_beta,
             const float* __restrict__ item_beta,
             const float* __restrict__ theta_user_visual,
             const float* __restrict__ theta_user_text,
             const float* __restrict__ visual_features,
             const float* __restrict__ textural_features,
             const int*   __restrict__ user_idx,
             const int*   __restrict__ item_idx,
             const int*   __restrict__ path_type,
             float* __restrict__ out,
             int B)
{
    const int b   = blockIdx.x;
    const int tid = threadIdx.x;           // 0..127

    __shared__ int   pt[PL];
    __shared__ float wsum[VEC / 32];

    const int u = user_idx[b];
    const int i = item_idx[b];

    if (tid < PL) pt[tid] = path_type[b * PL + tid];

    const uint64_t pol = policy_evict_last();

    const float4* ug_p = (const float4*)(user_gama         + (size_t)u * HIDDEN);
    const float4* ig_p = (const float4*)(item_gama         + (size_t)i * HIDDEN);
    const float4* tv_p = (const float4*)(theta_user_visual + (size_t)u * HIDDEN);
    const float4* tt_p = (const float4*)(theta_user_text   + (size_t)u * HIDDEN);
    const float4* vf_p = (const float4*)(visual_features   + (size_t)b * HIDDEN);
    const float4* tf_p = (const float4*)(textural_features + (size_t)b * HIDDEN);

    // Front-batch all six loads, all pinned evict_last in L2.
    const float4 ug4 = ld_el(&ug_p[tid], pol);
    const float4 ig4 = ld_el(&ig_p[tid], pol);
    const float4 tv4 = ld_el(&tv_p[tid], pol);
    const float4 tt4 = ld_el(&tt_p[tid], pol);
    const float4 vf4 = ld_el(&vf_p[tid], pol);
    const float4 tf4 = ld_el(&tf_p[tid], pol);

    // Dot products + warp reduce
    float partial =
        ug4.x * ig4.x + ug4.y * ig4.y + ug4.z * ig4.z + ug4.w * ig4.w +
        tv4.x * vf4.x + tv4.y * vf4.y + tv4.z * vf4.z + tv4.w * vf4.w +
        tt4.x * tf4.x + tt4.y * tf4.y + tt4.z * tf4.z + tt4.w * tf4.w;

    #pragma unroll
    for (int off = 16; off > 0; off >>= 1)
        partial += __shfl_xor_sync(0xFFFFFFFFu, partial, off);

    if ((tid & 31) == 0) wsum[tid >> 5] = partial;
    __syncthreads();

    if (tid == 0) {
        float s = user_beta[u] + item_beta[i];
        #pragma unroll
        for (int w = 0; w < VEC / 32; w++) s += wsum[w];
        out[b] = s;
    }

    // Metapath scatter: 16 coalesced STG.128 per thread, normal priority
    // (cannot evict the evict_last read set).
    float4* mp = (float4*)(out + B + (size_t)b * PL * HIDDEN);
    const float4 zero4 = make_float4(0.f, 0.f, 0.f, 0.f);

    #pragma unroll
    for (int j = 0; j < PL; j++) {
        const int t = pt[j];
        const float4 v = (t == 0) ? ug4 : ((t == 1) ? ig4 : zero4);
        mp[(size_t)j * VEC + tid] = v;
    }
}

extern "C" void kernel_launch(void* const* d_in, const int* in_sizes, int n_in,
                              void* d_out, int out_size)
{
    const float* user_gama          = (const float*)d_in[0];
    const float* item_gama          = (const float*)d_in[1];
    const float* user_beta          = (const float*)d_in[2];
    const float* item_beta          = (const float*)d_in[3];
    const float* theta_user_visual  = (const float*)d_in[4];
    const float* theta_user_text    = (const float*)d_in[5];
    const float* visual_features    = (const float*)d_in[6];
    const float* textural_features  = (const float*)d_in[7];
    const int*   user_idx           = (const int*)d_in[8];
    const int*   item_idx           = (const int*)d_in[9];
    const int*   path_type          = (const int*)d_in[10];

    const int B = in_sizes[8];  // 8192

    vtbpr_kernel<<<B, VEC>>>(user_gama, item_gama, user_beta, item_beta,
                             theta_user_visual, theta_user_text,
                             visual_features, textural_features,
                             user_idx, item_idx, path_type,
                             (float*)d_out, B);
}